// round 4
// baseline (speedup 1.0000x reference)
#include <cuda_runtime.h>

// Problem constants
#define DD     10000   // hypervector dimensions
#define TT     128     // time steps
#define CC     32      // channels
#define LL     21      // levels
#define LP     24      // padded levels (float4-friendly, pad = 0)
#define BBATCH 4
#define NCLS   10
#define NWIN   125     // T - NGRAM + 1
#define TD     128     // d-tile per block
#define HALO   3       // n-gram roll halo (shifts 3,2,1,0)
#define NCOL   (TD + HALO)
#define SSTR   132     // smem row stride for samples tile (bytes)
#define NTILES ((DD + TD - 1) / TD)   // 79

// Scratch (device globals — no allocation allowed)
__device__ float g_cnt[BBATCH * TT * LP];            // per-(b,t) level histogram, fp32
__device__ float g_partial[BBATCH * NTILES * NCLS];  // per-tile class partials

// ---------------------------------------------------------------------------
// Kernel 1: level-index histogram per (b,t). 512 threads total.
// idx = clip(round_half_even(x/HIGH*(L-1)), 0, 20);  x/20*20 mirrors reference fp.
// ---------------------------------------------------------------------------
__global__ void k_count(const float* __restrict__ x) {
    int b = blockIdx.x, t = threadIdx.x;
    const float* xp = x + (b * TT + t) * CC;
    int lvl[CC];
#pragma unroll
    for (int c = 0; c < CC; c++) {
        float v = (xp[c] / 20.0f) * 20.0f;      // HIGH=20, NUM_LEVELS-1=20
        int iv = __float2int_rn(v);              // round half-to-even == jnp.round
        iv = iv < 0 ? 0 : (iv > LL - 1 ? LL - 1 : iv);
        lvl[c] = iv;
    }
    float* out = &g_cnt[(b * TT + t) * LP];
#pragma unroll
    for (int l = 0; l < LL; l++) {
        int cnt = 0;
#pragma unroll
        for (int c = 0; c < CC; c++) cnt += (lvl[c] == l);
        out[l] = (float)cnt;
    }
    out[21] = 0.f; out[22] = 0.f; out[23] = 0.f;
}

// ---------------------------------------------------------------------------
// Kernel 2: fused samples + n-gram bind/bundle + hard-quantize + classify.
// Block = (d-tile, b). Phase A: build int8 samples tile [T][TD+3] in smem.
// Phase B: per output d, acc = sum_i prod_k ss[i+k][j+k]  (roll diagonals).
// Phase C: enc = sign(acc); fold into +-classify_w, block-reduce to partials.
// ---------------------------------------------------------------------------
__global__ __launch_bounds__(TD) void k_main(const float* __restrict__ signals_w,
                                             const float* __restrict__ timestamps_w,
                                             const float* __restrict__ classify_w) {
    __shared__ __align__(16) float cnt_s[TT * LP];   // 12288 B
    __shared__ signed char ss[TT * SSTR];            // 16896 B
    __shared__ float wsum[4][NCLS];                  // 160 B

    const int tile = blockIdx.x, b = blockIdx.y;
    const int tid = threadIdx.x;
    const int d0 = tile * TD;

    // load this batch's histograms (uniform across block)
    for (int i = tid; i < TT * LP; i += TD) cnt_s[i] = g_cnt[b * TT * LP + i];
    __syncthreads();

    // Phase A: one smem column per thread (+3 leftover columns to tid 0..2)
    for (int col = tid; col < NCOL; col += TD) {
        int dp = d0 - HALO + col;
        if (dp < 0)   dp += DD;    // roll wrap-around
        if (dp >= DD) dp -= DD;
        float sig[LP];
#pragma unroll
        for (int l = 0; l < LL; l++) sig[l] = signals_w[l * DD + dp];
        sig[21] = 0.f; sig[22] = 0.f; sig[23] = 0.f;

        for (int t = 0; t < TT; t++) {
            const float4* cr = (const float4*)&cnt_s[t * LP];
            float a0 = 0.f, a1 = 0.f, a2 = 0.f, a3 = 0.f;
#pragma unroll
            for (int m = 0; m < 6; m++) {
                float4 c = cr[m];
                a0 += c.x * sig[4 * m + 0];
                a1 += c.y * sig[4 * m + 1];
                a2 += c.z * sig[4 * m + 2];
                a3 += c.w * sig[4 * m + 3];
            }
            float s  = (a0 + a1) + (a2 + a3);          // integer-valued, exact
            float tw = timestamps_w[t * DD + dp];      // +-1
            ss[t * SSTR + col] = (signed char)__float2int_rn(tw * s); // [-32,32]
        }
    }
    __syncthreads();

    // Phase B: n-gram products along roll diagonals, exact int32
    const int d = d0 + tid;
    const bool active = (d < DD);
    int acc = 0;
    if (active) {
#pragma unroll 5
        for (int i = 0; i < NWIN; i++) {
            int p0 = ss[(i + 0) * SSTR + tid + 0];
            int p1 = ss[(i + 1) * SSTR + tid + 1];
            int p2 = ss[(i + 2) * SSTR + tid + 2];
            int p3 = ss[(i + 3) * SSTR + tid + 3];
            acc += p0 * p1 * p2 * p3;
        }
    }

    // Phase C: enc = (acc > 0) ? +1 : -1 ; fold into classify weights
    float val[NCLS];
#pragma unroll
    for (int n = 0; n < NCLS; n++) {
        float w = active ? classify_w[n * DD + d] : 0.f;
        val[n] = (acc > 0) ? w : -w;   // inactive: w=0 -> contributes 0
    }
#pragma unroll
    for (int n = 0; n < NCLS; n++) {
#pragma unroll
        for (int off = 16; off > 0; off >>= 1)
            val[n] += __shfl_down_sync(0xffffffffu, val[n], off);
    }
    const int warp = tid >> 5, lane = tid & 31;
    if (lane == 0) {
#pragma unroll
        for (int n = 0; n < NCLS; n++) wsum[warp][n] = val[n];
    }
    __syncthreads();
    if (tid < NCLS) {
        float s = wsum[0][tid] + wsum[1][tid] + wsum[2][tid] + wsum[3][tid];
        g_partial[(b * NTILES + tile) * NCLS + tid] = s;
    }
}

// ---------------------------------------------------------------------------
// Kernel 3: deterministic fixed-order reduction of tile partials -> d_out
// ---------------------------------------------------------------------------
__global__ void k_final(float* __restrict__ out) {
    int tid = threadIdx.x;
    if (tid < BBATCH * NCLS) {
        int b = tid / NCLS, n = tid % NCLS;
        float s = 0.f;
        for (int t = 0; t < NTILES; t++)
            s += g_partial[(b * NTILES + t) * NCLS + n];
        out[b * NCLS + n] = s;
    }
}

extern "C" void kernel_launch(void* const* d_in, const int* in_sizes, int n_in,
                              void* d_out, int out_size) {
    const float* x            = (const float*)d_in[0];  // [4,128,32]
    const float* signals_w    = (const float*)d_in[1];  // [21,10000]
    // d_in[2] = channels_w : dead bind in reference, intentionally unused
    const float* timestamps_w = (const float*)d_in[3];  // [128,10000]
    const float* classify_w   = (const float*)d_in[4];  // [10,10000]
    float* out = (float*)d_out;                         // [4,10] fp32

    k_count<<<BBATCH, TT>>>(x);
    k_main<<<dim3(NTILES, BBATCH), TD>>>(signals_w, timestamps_w, classify_w);
    k_final<<<1, 64>>>(out);
}

// round 5
// speedup vs baseline: 1.5741x; 1.5741x over previous
#include <cuda_runtime.h>

#define DD     10000   // hypervector dimensions
#define TT     128     // time steps
#define CC     32      // channels
#define BB     4       // batch
#define NCLS   10
#define NWIN   125     // T - NGRAM + 1
#define TD     125     // d-tile per block (DD/TD = 80 exactly)
#define NTILES 80
#define NBLK   (NTILES * BB)   // 320

// Scratch (device globals — no allocation allowed; zero-initialized at load)
__device__ float    g_partial[BB * NTILES * NCLS];
__device__ unsigned g_ticket;

// ---------------------------------------------------------------------------
// Single fused kernel.
//  Hist : per-block, thread t builds packed int8 level-histogram (21 levels in
//         6 words, ≤32 per byte) for its batch b in smem.
//  A    : thread = one d-column (col 0..127 maps to d0-3+col, roll wrap).
//         samples[t][col] = sign(ts_w) * dp4a(counts[t], signal_signs[col]),
//         stored as int8 in smem [128 x 128].
//  B    : n-gram bind along roll diagonals, exact int32.
//  C    : hard-quantize -> fold +-classify_w, block reduce -> tile partial.
//  Tail : last block (atomic ticket) reduces 80 tile partials in fixed order.
// ---------------------------------------------------------------------------
__global__ __launch_bounds__(128) void k_fused(
    const float* __restrict__ x,
    const float* __restrict__ signals_w,
    const float* __restrict__ timestamps_w,
    const float* __restrict__ classify_w,
    float* __restrict__ out)
{
    __shared__ __align__(16) unsigned cnt_s[TT * 8];   // 4 KB: 6 count words + 2 pad per t
    __shared__ signed char ss[TT * 128];               // 16 KB samples tile
    __shared__ float wsum[4][NCLS];
    __shared__ int   last_flag;

    const int tid  = threadIdx.x;
    const int tile = blockIdx.x;
    const int b    = blockIdx.y;
    const int d0   = tile * TD;

    // --- Histogram for t = tid (each thread owns its smem row; no races) ---
    {
        uint4 z = make_uint4(0u, 0u, 0u, 0u);
        *(uint4*)&cnt_s[tid * 8]     = z;
        *(uint4*)&cnt_s[tid * 8 + 4] = z;
        const float* xp = x + (b * TT + tid) * CC;
#pragma unroll
        for (int c = 0; c < CC; c++) {
            float v = (xp[c] / 20.0f) * 20.0f;   // mirrors reference fp exactly
            int iv = __float2int_rn(v);          // round half-to-even == jnp.round
            iv = iv < 0 ? 0 : (iv > 20 ? 20 : iv);
            cnt_s[tid * 8 + (iv >> 2)] += 1u << ((iv & 3) * 8);
        }
    }

    // --- Pack this column's 21 signal signs as int8 bytes (+1 / -1) ---
    int dp = d0 - 3 + tid;           // roll halo; only tile 0 can go negative
    if (dp < 0) dp += DD;
    unsigned sw[6] = {0u, 0u, 0u, 0u, 0u, 0u};
#pragma unroll
    for (int l = 0; l < 21; l++) {
        unsigned neg  = __float_as_uint(signals_w[l * DD + dp]) >> 31;
        unsigned byte = neg ? 0xFFu : 0x01u;
        sw[l >> 2] |= byte << ((l & 3) * 8);
    }
    const int sp0 = (int)sw[0], sp1 = (int)sw[1], sp2 = (int)sw[2];
    const int sp3 = (int)sw[3], sp4 = (int)sw[4], sp5 = (int)sw[5];
    __syncthreads();

    // --- Phase A: samples tile, dp4a + MLP-4 timestamp loads ---
#pragma unroll 4
    for (int t = 0; t < TT; t++) {
        uint4 ca = *(const uint4*)&cnt_s[t * 8];       // broadcast LDS
        uint2 cb = *(const uint2*)&cnt_s[t * 8 + 4];
        int acc = 0;
        acc = __dp4a((int)ca.x, sp0, acc);
        acc = __dp4a((int)ca.y, sp1, acc);
        acc = __dp4a((int)ca.z, sp2, acc);
        acc = __dp4a((int)ca.w, sp3, acc);
        acc = __dp4a((int)cb.x, sp4, acc);
        acc = __dp4a((int)cb.y, sp5, acc);
        unsigned tb = __float_as_uint(timestamps_w[t * DD + dp]);  // +-1 sign bit
        int v = (tb >> 31) ? -acc : acc;               // |v| <= 32
        ss[t * 128 + tid] = (signed char)v;
    }
    __syncthreads();

    // --- Phase B: n-gram products along roll diagonals (exact int32) ---
    int acc = 0;
    if (tid < TD) {
#pragma unroll 5
        for (int i = 0; i < NWIN; i++) {
            int p0 = ss[(i + 0) * 128 + tid + 0];
            int p1 = ss[(i + 1) * 128 + tid + 1];
            int p2 = ss[(i + 2) * 128 + tid + 2];
            int p3 = ss[(i + 3) * 128 + tid + 3];
            acc += p0 * p1 * p2 * p3;
        }
    }

    // --- Phase C: enc = sign(acc); fold classify weights; block reduce ---
    const int d = d0 + tid;
    float val[NCLS];
#pragma unroll
    for (int n = 0; n < NCLS; n++) {
        float wv = (tid < TD) ? classify_w[n * DD + d] : 0.f;
        val[n] = (acc > 0) ? wv : -wv;     // inactive lanes contribute 0
    }
#pragma unroll
    for (int n = 0; n < NCLS; n++) {
#pragma unroll
        for (int off = 16; off > 0; off >>= 1)
            val[n] += __shfl_down_sync(0xffffffffu, val[n], off);
    }
    const int warp = tid >> 5, lane = tid & 31;
    if (lane == 0) {
#pragma unroll
        for (int n = 0; n < NCLS; n++) wsum[warp][n] = val[n];
    }
    __syncthreads();
    if (tid < NCLS) {
        float s = wsum[0][tid] + wsum[1][tid] + wsum[2][tid] + wsum[3][tid];
        g_partial[(b * NTILES + tile) * NCLS + tid] = s;
    }

    // --- Deterministic last-block final reduction (fixed tile order) ---
    __threadfence();
    __syncthreads();
    if (tid == 0) {
        unsigned tk = atomicAdd(&g_ticket, 1u);
        last_flag = (tk == NBLK - 1);
    }
    __syncthreads();
    if (last_flag) {
        if (tid == 0) g_ticket = 0;        // reset for next graph replay
        __threadfence();
        if (tid < BB * NCLS) {
            int bb = tid / NCLS, n = tid % NCLS;
            float s = 0.f;
            for (int t2 = 0; t2 < NTILES; t2++)
                s += g_partial[(bb * NTILES + t2) * NCLS + n];
            out[bb * NCLS + n] = s;
        }
    }
}

extern "C" void kernel_launch(void* const* d_in, const int* in_sizes, int n_in,
                              void* d_out, int out_size) {
    const float* x            = (const float*)d_in[0];  // [4,128,32]
    const float* signals_w    = (const float*)d_in[1];  // [21,10000]
    // d_in[2] = channels_w : dead bind in reference, intentionally unused
    const float* timestamps_w = (const float*)d_in[3];  // [128,10000]
    const float* classify_w   = (const float*)d_in[4];  // [10,10000]
    float* out = (float*)d_out;                         // [4,10] fp32

    k_fused<<<dim3(NTILES, BB), 128>>>(x, signals_w, timestamps_w, classify_w, out);
}

// round 6
// speedup vs baseline: 2.2184x; 1.4093x over previous
#include <cuda_runtime.h>

#define DD     10000   // hypervector dimensions
#define TT     128     // time steps
#define CC     32      // channels
#define BB     4       // batch
#define NCLS   10
#define NWIN   125     // T - NGRAM + 1
#define TD     125     // d-tile per block (DD/TD = 80 exactly)
#define NTILES 80
#define NBLK   (NTILES * BB)   // 320

// Scratch (device globals — no allocation allowed; zero-initialized at load)
__device__ float    g_partial[BB * NTILES * NCLS];
__device__ unsigned g_ticket;

// ---------------------------------------------------------------------------
// One fused kernel, 512 threads/block: col = tid&127 (d-column), q = tid>>7.
//  Setup (parallel): warps 0-3 build per-t packed histograms;
//                    warps 4-7 pack per-column signal signs (int8 +-1) to smem.
//  A: thread (col,q) fills t-rows [32q, 32q+32) of int8 samples tile.
//  B: thread (col,q) reduces its quarter of the 125 n-gram windows (int32).
//  C: warps 0-3 combine quarters, hard-quantize, fold +-classify_w, reduce.
//  Tail: last block (ticket) reduces tile partials in fixed order.
// ---------------------------------------------------------------------------
__global__ __launch_bounds__(512) void k_fused(
    const float* __restrict__ x,
    const float* __restrict__ signals_w,
    const float* __restrict__ timestamps_w,
    const float* __restrict__ classify_w,
    float* __restrict__ out)
{
    __shared__ __align__(16) unsigned cnt_s[TT * 8];   // 4 KB: 6 count words + pad per t
    __shared__ int sw_s[6][TT];                        // 3 KB packed signal signs per column
    __shared__ signed char ss[TT * 128];               // 16 KB samples tile
    __shared__ int   acc_s[4][128];                    // 2 KB window-quarter partials
    __shared__ float wsum[4][NCLS];
    __shared__ int   last_flag;

    const int tid  = threadIdx.x;
    const int col  = tid & 127;
    const int q    = tid >> 7;          // 0..3
    const int tile = blockIdx.x;
    const int b    = blockIdx.y;
    const int d0   = tile * TD;

    int dp = d0 - 3 + col;              // roll halo; only tile 0 wraps
    if (dp < 0) dp += DD;

    if (q == 0) {
        // --- Histogram for t = col (packed: 21 levels, <=32 per byte) ---
        uint4 z = make_uint4(0u, 0u, 0u, 0u);
        *(uint4*)&cnt_s[col * 8]     = z;
        *(uint4*)&cnt_s[col * 8 + 4] = z;
        const float4* xp = (const float4*)(x + (b * TT + col) * CC);
#pragma unroll
        for (int c4 = 0; c4 < CC / 4; c4++) {
            float4 v4 = xp[c4];
            float vv[4] = {v4.x, v4.y, v4.z, v4.w};
#pragma unroll
            for (int j = 0; j < 4; j++) {
                float v = (vv[j] / 20.0f) * 20.0f;   // mirrors reference fp exactly
                int iv = __float2int_rn(v);          // round half-to-even == jnp.round
                iv = iv < 0 ? 0 : (iv > 20 ? 20 : iv);
                cnt_s[col * 8 + (iv >> 2)] += 1u << ((iv & 3) * 8);
            }
        }
    } else if (q == 1) {
        // --- Pack column col's 21 signal signs as int8 bytes (+1 / -1) ---
        unsigned sw[6] = {0u, 0u, 0u, 0u, 0u, 0u};
#pragma unroll
        for (int l = 0; l < 21; l++) {
            unsigned neg  = __float_as_uint(signals_w[l * DD + dp]) >> 31;
            unsigned byte = neg ? 0xFFu : 0x01u;
            sw[l >> 2] |= byte << ((l & 3) * 8);
        }
#pragma unroll
        for (int l = 0; l < 6; l++) sw_s[l][col] = (int)sw[l];
    }
    __syncthreads();

    const int sp0 = sw_s[0][col], sp1 = sw_s[1][col], sp2 = sw_s[2][col];
    const int sp3 = sw_s[3][col], sp4 = sw_s[4][col], sp5 = sw_s[5][col];

    // --- Phase A: 32 t-rows per thread, dp4a + MLP-4 timestamp loads ---
    const int t0 = q * 32;
#pragma unroll 4
    for (int tt = 0; tt < 32; tt++) {
        const int t = t0 + tt;
        uint4 ca = *(const uint4*)&cnt_s[t * 8];       // broadcast LDS
        uint2 cb = *(const uint2*)&cnt_s[t * 8 + 4];
        int acc = 0;
        acc = __dp4a((int)ca.x, sp0, acc);
        acc = __dp4a((int)ca.y, sp1, acc);
        acc = __dp4a((int)ca.z, sp2, acc);
        acc = __dp4a((int)ca.w, sp3, acc);
        acc = __dp4a((int)cb.x, sp4, acc);
        acc = __dp4a((int)cb.y, sp5, acc);
        unsigned tb = __float_as_uint(timestamps_w[t * DD + dp]);  // +-1 sign bit
        int v = (tb >> 31) ? -acc : acc;               // |v| <= 32
        ss[t * 128 + col] = (signed char)v;
    }
    __syncthreads();

    // --- Phase B: quarter of the windows per thread (exact int32) ---
    {
        const int istart = q * 31 + (q > 0 ? 1 : 0);   // 0,32,63,94
        const int icnt   = (q == 0) ? 32 : 31;
        int acc = 0;
        if (col < TD) {
#pragma unroll 4
            for (int ii = 0; ii < icnt; ii++) {
                const int i = istart + ii;
                int p0 = ss[(i + 0) * 128 + col + 0];
                int p1 = ss[(i + 1) * 128 + col + 1];
                int p2 = ss[(i + 2) * 128 + col + 2];
                int p3 = ss[(i + 3) * 128 + col + 3];
                acc += p0 * p1 * p2 * p3;
            }
        }
        acc_s[q][col] = acc;
    }
    __syncthreads();

    // --- Phase C: combine, hard-quantize, fold classify weights, reduce ---
    if (q == 0) {
        const int acc = acc_s[0][col] + acc_s[1][col] + acc_s[2][col] + acc_s[3][col];
        const int d = d0 + col;
        float val[NCLS];
#pragma unroll
        for (int n = 0; n < NCLS; n++) {
            float wv = (col < TD) ? classify_w[n * DD + d] : 0.f;
            val[n] = (acc > 0) ? wv : -wv;     // inactive lanes contribute 0
        }
#pragma unroll
        for (int n = 0; n < NCLS; n++) {
#pragma unroll
            for (int off = 16; off > 0; off >>= 1)
                val[n] += __shfl_down_sync(0xffffffffu, val[n], off);
        }
        const int warp = col >> 5, lane = col & 31;
        if (lane == 0) {
#pragma unroll
            for (int n = 0; n < NCLS; n++) wsum[warp][n] = val[n];
        }
    }
    __syncthreads();
    if (tid < NCLS) {
        float s = wsum[0][tid] + wsum[1][tid] + wsum[2][tid] + wsum[3][tid];
        g_partial[(b * NTILES + tile) * NCLS + tid] = s;
    }

    // --- Deterministic last-block final reduction (fixed tile order) ---
    __threadfence();
    __syncthreads();
    if (tid == 0) {
        unsigned tk = atomicAdd(&g_ticket, 1u);
        last_flag = (tk == NBLK - 1);
    }
    __syncthreads();
    if (last_flag) {
        if (tid == 0) g_ticket = 0;        // reset for next graph replay
        __threadfence();
        if (tid < BB * NCLS) {
            int bb = tid / NCLS, n = tid % NCLS;
            float s = 0.f;
            for (int t2 = 0; t2 < NTILES; t2++)
                s += g_partial[(bb * NTILES + t2) * NCLS + n];
            out[bb * NCLS + n] = s;
        }
    }
}

extern "C" void kernel_launch(void* const* d_in, const int* in_sizes, int n_in,
                              void* d_out, int out_size) {
    const float* x            = (const float*)d_in[0];  // [4,128,32]
    const float* signals_w    = (const float*)d_in[1];  // [21,10000]
    // d_in[2] = channels_w : dead bind in reference, intentionally unused
    const float* timestamps_w = (const float*)d_in[3];  // [128,10000]
    const float* classify_w   = (const float*)d_in[4];  // [10,10000]
    float* out = (float*)d_out;                         // [4,10] fp32

    k_fused<<<dim3(NTILES, BB), 512>>>(x, signals_w, timestamps_w, classify_w, out);
}

// round 10
// speedup vs baseline: 2.2215x; 1.0014x over previous
#include <cuda_runtime.h>

#define DD     10000   // hypervector dimensions
#define TT     128     // time steps
#define CC     32      // channels
#define BB     4       // batch
#define NCLS   10
#define NWIN   125     // T - NGRAM + 1
#define TD     125     // d-tile per block (DD/TD = 80 exactly)
#define NTILES 80
#define NBLK   (NTILES * BB)   // 320

// Scratch (device globals — no allocation allowed; zero-initialized at load)
__device__ float    g_partial[BB * NTILES * NCLS];
__device__ unsigned g_ticket;

// ---------------------------------------------------------------------------
// Fused kernel, 512 threads = 16 warps: col = tid&127, q = tid>>7 (t-quarter),
// warp w = tid>>5 factors as (class-group w>>2 == q) x (col-group w&3).
//  Pre  : each thread packs its 32 timestamp sign bits into ONE uint (MLP=32)
//         and preloads its <=3 classify weights — all global latency up front.
//  Setup: q==0 warps build packed per-t histograms; q==1 warps pack signal
//         signs (int8 +-1, 6 words) per column.
//  A    : thread (col,q) computes t-rows [32q,32q+32) via dp4a (NO global
//         loads) into the row-major int8 samples tile.
//  B    : thread (col,q) reduces its quarter of the 125 n-gram windows
//         (int32, exact) along roll diagonals.
//  C    : all 16 warps: combine quarters, hard-quantize, fold +-classify_w.
//         Class split 3/3/3/1 over q-groups; col split over w&3. Each
//         (class, col-group) owned by exactly one warp. Shuffle-reduce.
//  Tail : last block (ticket) reduces 80 tile partials in fixed order.
// ---------------------------------------------------------------------------
__global__ __launch_bounds__(512) void k_fused(
    const float* __restrict__ x,
    const float* __restrict__ signals_w,
    const float* __restrict__ timestamps_w,
    const float* __restrict__ classify_w,
    float* __restrict__ out)
{
    __shared__ __align__(16) unsigned cnt_s[TT * 8];   // 4 KB packed histograms
    __shared__ int sw_s[6][TT];                        // 3 KB packed signal signs
    __shared__ signed char ss[TT * 128];               // 16 KB row-major samples
    __shared__ int   acc_s[4][128];                    // window-quarter partials
    __shared__ float wsum2[NCLS][4];                   // per-(class, col-group)
    __shared__ int   last_flag;

    const int tid  = threadIdx.x;
    const int col  = tid & 127;
    const int q    = tid >> 7;          // 0..3 -> t-range [32q, 32q+32)
    const int cg   = (tid >> 5) & 3;    // col-group 0..3 (col == cg*32 + lane)
    const int tile = blockIdx.x;
    const int b    = blockIdx.y;
    const int d0   = tile * TD;
    const int t0   = q * 32;

    int dp = d0 - 3 + col;              // roll halo; only tile 0 wraps
    if (dp < 0) dp += DD;

    // --- Pre: 32 timestamp sign bits -> one word (all LDG latency here) ---
    unsigned tsbits = 0;
#pragma unroll
    for (int tt = 0; tt < 32; tt++)
        tsbits |= (__float_as_uint(timestamps_w[(t0 + tt) * DD + dp]) >> 31) << tt;

    // --- Pre: classify weights. Class-group q owns classes 3q..min(3q+2,9) ---
    const int n0 = 3 * q;               // 0,3,6,9 ; sizes 3/3/3/1
    float cw[3];
#pragma unroll
    for (int j = 0; j < 3; j++) {
        const int n = n0 + j;
        cw[j] = (n < NCLS && col < TD) ? classify_w[n * DD + d0 + col] : 0.f;
    }

    if (q == 0) {
        // --- Histogram for t = col (packed: 21 levels, <=32 per byte) ---
        uint4 z = make_uint4(0u, 0u, 0u, 0u);
        *(uint4*)&cnt_s[col * 8]     = z;
        *(uint4*)&cnt_s[col * 8 + 4] = z;
        const float4* xp = (const float4*)(x + (b * TT + col) * CC);
#pragma unroll
        for (int c4 = 0; c4 < CC / 4; c4++) {
            float4 v4 = xp[c4];
            float vv[4] = {v4.x, v4.y, v4.z, v4.w};
#pragma unroll
            for (int j = 0; j < 4; j++) {
                float v = (vv[j] / 20.0f) * 20.0f;   // mirrors reference fp exactly
                int iv = __float2int_rn(v);          // round half-to-even == jnp.round
                iv = iv < 0 ? 0 : (iv > 20 ? 20 : iv);
                cnt_s[col * 8 + (iv >> 2)] += 1u << ((iv & 3) * 8);
            }
        }
    } else if (q == 1) {
        // --- Pack column col's 21 signal signs as int8 bytes (+1 / -1) ---
        unsigned sw[6] = {0u, 0u, 0u, 0u, 0u, 0u};
#pragma unroll
        for (int l = 0; l < 21; l++) {
            unsigned neg  = __float_as_uint(signals_w[l * DD + dp]) >> 31;
            unsigned byte = neg ? 0xFFu : 0x01u;
            sw[l >> 2] |= byte << ((l & 3) * 8);
        }
#pragma unroll
        for (int l = 0; l < 6; l++) sw_s[l][col] = (int)sw[l];
    }
    __syncthreads();

    const int sp0 = sw_s[0][col], sp1 = sw_s[1][col], sp2 = sw_s[2][col];
    const int sp3 = sw_s[3][col], sp4 = sw_s[4][col], sp5 = sw_s[5][col];

    // --- Phase A: 32 t-rows, dp4a only, no global loads (row-major STS.8) ---
#pragma unroll 4
    for (int tt = 0; tt < 32; tt++) {
        const int t = t0 + tt;
        uint4 ca = *(const uint4*)&cnt_s[t * 8];       // broadcast LDS
        uint2 cb = *(const uint2*)&cnt_s[t * 8 + 4];
        int a = 0;
        a = __dp4a((int)ca.x, sp0, a);
        a = __dp4a((int)ca.y, sp1, a);
        a = __dp4a((int)ca.z, sp2, a);
        a = __dp4a((int)ca.w, sp3, a);
        a = __dp4a((int)cb.x, sp4, a);
        a = __dp4a((int)cb.y, sp5, a);
        int v = ((tsbits >> tt) & 1u) ? -a : a;        // |v| <= 32
        ss[t * 128 + col] = (signed char)v;
    }
    __syncthreads();

    // --- Phase B: quarter of the windows per thread (exact int32) ---
    {
        const int istart = q * 31 + (q > 0 ? 1 : 0);   // 0,32,63,94
        const int icnt   = (q == 0) ? 32 : 31;
        int acc = 0;
        if (col < TD) {
#pragma unroll 4
            for (int ii = 0; ii < icnt; ii++) {
                const int i = istart + ii;
                int p0 = ss[(i + 0) * 128 + col + 0];
                int p1 = ss[(i + 1) * 128 + col + 1];
                int p2 = ss[(i + 2) * 128 + col + 2];
                int p3 = ss[(i + 3) * 128 + col + 3];
                acc += p0 * p1 * p2 * p3;
            }
        }
        acc_s[q][col] = acc;
    }
    __syncthreads();

    // --- Phase C: all 16 warps; <=3 classes each; shuffle reduce ---
    {
        const int acc = acc_s[0][col] + acc_s[1][col] + acc_s[2][col] + acc_s[3][col];
        float val[3];
#pragma unroll
        for (int j = 0; j < 3; j++)
            val[j] = (acc > 0) ? cw[j] : -cw[j];   // inactive/padded lanes hold 0
#pragma unroll
        for (int j = 0; j < 3; j++) {
#pragma unroll
            for (int off = 16; off > 0; off >>= 1)
                val[j] += __shfl_down_sync(0xffffffffu, val[j], off);
        }
        if ((tid & 31) == 0) {
#pragma unroll
            for (int j = 0; j < 3; j++) {
                const int n = n0 + j;
                if (n < NCLS) wsum2[n][cg] = val[j];
            }
        }
    }
    __syncthreads();
    if (tid < NCLS) {
        float s = wsum2[tid][0] + wsum2[tid][1] + wsum2[tid][2] + wsum2[tid][3];
        g_partial[(b * NTILES + tile) * NCLS + tid] = s;
    }

    // --- Deterministic last-block final reduction (fixed tile order) ---
    __threadfence();
    __syncthreads();
    if (tid == 0) {
        unsigned tk = atomicAdd(&g_ticket, 1u);
        last_flag = (tk == NBLK - 1);
    }
    __syncthreads();
    if (last_flag) {
        if (tid == 0) g_ticket = 0;        // reset for next graph replay
        __threadfence();
        if (tid < BB * NCLS) {
            int bb = tid / NCLS, n = tid % NCLS;
            float s = 0.f;
#pragma unroll 8
            for (int t2 = 0; t2 < NTILES; t2++)
                s += g_partial[(bb * NTILES + t2) * NCLS + n];
            out[bb * NCLS + n] = s;
        }
    }
}

extern "C" void kernel_launch(void* const* d_in, const int* in_sizes, int n_in,
                              void* d_out, int out_size) {
    const float* x            = (const float*)d_in[0];  // [4,128,32]
    const float* signals_w    = (const float*)d_in[1];  // [21,10000]
    // d_in[2] = channels_w : dead bind in reference, intentionally unused
    const float* timestamps_w = (const float*)d_in[3];  // [128,10000]
    const float* classify_w   = (const float*)d_in[4];  // [10,10000]
    float* out = (float*)d_out;                         // [4,10] fp32

    k_fused<<<dim3(NTILES, BB), 512>>>(x, signals_w, timestamps_w, classify_w, out);
}